// round 2
// baseline (speedup 1.0000x reference)
#include <cuda_runtime.h>
#include <math.h>

#define EPSF 1e-6f
#define Bn 16
#define Cn 512
#define Nn 4096
#define Kn 64
#define NUM_STAGES 3
#define NCHUNK 8

// Scratch (no allocations allowed -> device globals)
__device__ float g_b[Bn * Cn * Kn];        // current bases       (2 MB)
__device__ float g_bnew[Bn * Cn * Kn];     // accumulator         (2 MB)
__device__ float g_att[Bn * Nn * Kn];      // softmax attention   (16 MB)
__device__ float g_colsum[Bn * Kn];        // sum over N per (b,k)

// ---------------------------------------------------------------------------
// Normalize bases (l2 over C) and broadcast to all batches.
// grid = Kn blocks, 128 threads.
__global__ void k_init(const float* __restrict__ bases) {
    int k = blockIdx.x;
    int tid = threadIdx.x;
    float s = 0.f;
    for (int c = tid; c < Cn; c += 128) {
        float v = bases[c * Kn + k];
        s += v * v;
    }
    __shared__ float sh[128];
    sh[tid] = s;
    __syncthreads();
    for (int o = 64; o > 0; o >>= 1) {
        if (tid < o) sh[tid] += sh[tid + o];
        __syncthreads();
    }
    float inv = 1.f / (EPSF + sqrtf(sh[0]));
    for (int c = tid; c < Cn; c += 128) {
        float v = bases[c * Kn + k] * inv;
        for (int b = 0; b < Bn; b++)
            g_b[(b * Cn + c) * Kn + k] = v;
    }
}

// ---------------------------------------------------------------------------
__global__ void k_zero() {
    int i = blockIdx.x * 256 + threadIdx.x;
    if (i < Bn * Cn * Kn) g_bnew[i] = 0.f;
    if (i < Bn * Kn) g_colsum[i] = 0.f;
}

// ---------------------------------------------------------------------------
// attention[b,n,k] = softmax_k( sum_c f[b,c,n] * g_b[b,c,k] )
// Also accumulates colsum[b,k] = sum_n attention[b,n,k].
// grid = (Nn/128, Bn), block 256. Tile: 128 n x 64 k, thread micro 8n x 4k.
__global__ __launch_bounds__(256) void k_att(const float* __restrict__ f) {
    int b = blockIdx.y;
    int n0 = blockIdx.x * 128;
    int tid = threadIdx.x;
    int kx = tid & 15;      // k quad index
    int nx = tid >> 4;      // n oct index

    __shared__ float sf[16 * 128];   // [cc][n]
    __shared__ float sb[16 * Kn];    // [cc][k]
    __shared__ float colsh[Kn];

    float acc[8][4];
#pragma unroll
    for (int r = 0; r < 8; r++)
#pragma unroll
        for (int j = 0; j < 4; j++) acc[r][j] = 0.f;

    const float* fb = f + (size_t)b * Cn * Nn;
    const float* bb = g_b + (b * Cn) * Kn;

    for (int c0 = 0; c0 < Cn; c0 += 16) {
#pragma unroll
        for (int t = 0; t < 2; t++) {
            int i = tid + t * 256;            // 0..511
            int cc = i >> 5, nn4 = i & 31;
            float4 v = *(const float4*)(fb + (size_t)(c0 + cc) * Nn + n0 + nn4 * 4);
            *(float4*)(sf + cc * 128 + nn4 * 4) = v;
        }
        {
            int cc = tid >> 4, k4 = tid & 15;
            float4 v = *(const float4*)(bb + (c0 + cc) * Kn + k4 * 4);
            *(float4*)(sb + cc * Kn + k4 * 4) = v;
        }
        __syncthreads();
#pragma unroll
        for (int cc = 0; cc < 16; cc++) {
            float4 a0 = *(float4*)(sf + cc * 128 + nx * 8);
            float4 a1 = *(float4*)(sf + cc * 128 + nx * 8 + 4);
            float4 bv = *(float4*)(sb + cc * Kn + kx * 4);
            float av[8] = {a0.x, a0.y, a0.z, a0.w, a1.x, a1.y, a1.z, a1.w};
            float bw[4] = {bv.x, bv.y, bv.z, bv.w};
#pragma unroll
            for (int r = 0; r < 8; r++)
#pragma unroll
                for (int j = 0; j < 4; j++) acc[r][j] += av[r] * bw[j];
        }
        __syncthreads();
    }

    // Softmax over k (row spans the 16 lanes sharing nx; xor 1,2,4,8 stays in group)
    float cp[4] = {0.f, 0.f, 0.f, 0.f};
    float* attb = g_att + ((size_t)b * Nn + n0) * Kn;
#pragma unroll
    for (int r = 0; r < 8; r++) {
        float m = fmaxf(fmaxf(acc[r][0], acc[r][1]), fmaxf(acc[r][2], acc[r][3]));
#pragma unroll
        for (int s = 1; s < 16; s <<= 1) m = fmaxf(m, __shfl_xor_sync(0xffffffffu, m, s));
        float e0 = __expf(acc[r][0] - m);
        float e1 = __expf(acc[r][1] - m);
        float e2 = __expf(acc[r][2] - m);
        float e3 = __expf(acc[r][3] - m);
        float s4 = e0 + e1 + e2 + e3;
#pragma unroll
        for (int s = 1; s < 16; s <<= 1) s4 += __shfl_xor_sync(0xffffffffu, s4, s);
        float inv = 1.f / s4;
        e0 *= inv; e1 *= inv; e2 *= inv; e3 *= inv;
        int n = nx * 8 + r;
        *(float4*)(attb + n * Kn + kx * 4) = make_float4(e0, e1, e2, e3);
        cp[0] += e0; cp[1] += e1; cp[2] += e2; cp[3] += e3;
    }

    __syncthreads();
    if (tid < Kn) colsh[tid] = 0.f;
    __syncthreads();
    atomicAdd(&colsh[kx * 4 + 0], cp[0]);
    atomicAdd(&colsh[kx * 4 + 1], cp[1]);
    atomicAdd(&colsh[kx * 4 + 2], cp[2]);
    atomicAdd(&colsh[kx * 4 + 3], cp[3]);
    __syncthreads();
    if (tid < Kn) atomicAdd(&g_colsum[b * Kn + tid], colsh[tid]);
}

// ---------------------------------------------------------------------------
// bnew[b,c,k] += sum_{n in chunk} f[b,c,n] * att[b,n,k]
// grid = (NCHUNK, Cn/128, Bn), block 256. Tile: 128 c x 64 k, micro 8c x 4k.
__global__ __launch_bounds__(256) void k_bnew(const float* __restrict__ f) {
    int b = blockIdx.z;
    int c0 = blockIdx.y * 128;
    int nbase0 = blockIdx.x * (Nn / NCHUNK);
    int tid = threadIdx.x;
    int kx = tid & 15;
    int cx = tid >> 4;

    __shared__ float sf[128 * 17];   // [c][nn], pad 17 -> conflict-free column reads
    __shared__ float sa[16 * Kn];    // [nn][k]

    float acc[8][4];
#pragma unroll
    for (int r = 0; r < 8; r++)
#pragma unroll
        for (int j = 0; j < 4; j++) acc[r][j] = 0.f;

    const float* fb = f + (size_t)b * Cn * Nn + (size_t)c0 * Nn;
    const float* ab = g_att + (size_t)b * Nn * Kn;

    for (int nb = nbase0; nb < nbase0 + Nn / NCHUNK; nb += 16) {
#pragma unroll
        for (int t = 0; t < 2; t++) {
            int i = tid + t * 256;          // 0..511
            int row = i >> 2, seg = i & 3;
            float4 v = *(const float4*)(fb + (size_t)row * Nn + nb + seg * 4);
            float* d = sf + row * 17 + seg * 4;
            d[0] = v.x; d[1] = v.y; d[2] = v.z; d[3] = v.w;
        }
        {
            int nn = tid >> 4, k4 = tid & 15;
            float4 v = *(const float4*)(ab + (size_t)(nb + nn) * Kn + k4 * 4);
            *(float4*)(sa + nn * Kn + k4 * 4) = v;
        }
        __syncthreads();
#pragma unroll
        for (int nn = 0; nn < 16; nn++) {
            float4 bv = *(float4*)(sa + nn * Kn + kx * 4);
            float bw[4] = {bv.x, bv.y, bv.z, bv.w};
#pragma unroll
            for (int r = 0; r < 8; r++) {
                float a = sf[(cx * 8 + r) * 17 + nn];
                acc[r][0] += a * bw[0];
                acc[r][1] += a * bw[1];
                acc[r][2] += a * bw[2];
                acc[r][3] += a * bw[3];
            }
        }
        __syncthreads();
    }

    float* outp = g_bnew + ((b * Cn) + c0) * Kn;
#pragma unroll
    for (int r = 0; r < 8; r++)
#pragma unroll
        for (int j = 0; j < 4; j++)
            atomicAdd(&outp[(cx * 8 + r) * Kn + kx * 4 + j], acc[r][j]);
}

// ---------------------------------------------------------------------------
// Fused l1norm (via colsum) + l2norm over C:
//   b = b' / ((EPS+cs)*EPS + sqrt(sum_c b'^2))
// grid = Bn*Kn blocks, 128 threads.
__global__ void k_bnorm() {
    int blk = blockIdx.x;
    int b = blk >> 6;
    int k = blk & 63;
    int tid = threadIdx.x;

    const float* src = g_bnew + (b * Cn) * Kn + k;
    float v[4];
    float s = 0.f;
#pragma unroll
    for (int i = 0; i < 4; i++) {
        v[i] = src[(tid + i * 128) * Kn];
        s += v[i] * v[i];
    }
    __shared__ float sh[128];
    sh[tid] = s;
    __syncthreads();
    for (int o = 64; o > 0; o >>= 1) {
        if (tid < o) sh[tid] += sh[tid + o];
        __syncthreads();
    }
    float cs = g_colsum[b * Kn + k];
    float inv = 1.f / ((EPSF + cs) * EPSF + sqrtf(sh[0]));
    float* dst = g_b + (b * Cn) * Kn + k;
#pragma unroll
    for (int i = 0; i < 4; i++) dst[(tid + i * 128) * Kn] = v[i] * inv;
}

// ---------------------------------------------------------------------------
// recon[b,c,n] = sum_k g_b[b,c,k] * att[b,n,k]
// grid = (Nn/128, Cn/64, Bn), block 256. Tile 64c x 128n, micro 8c x 4n.
__global__ __launch_bounds__(256) void k_recon(float* __restrict__ out) {
    int b = blockIdx.z;
    int c0 = blockIdx.y * 64;
    int n0 = blockIdx.x * 128;
    int tid = threadIdx.x;
    int nx = tid & 31;    // n quad
    int cy = tid >> 5;    // c oct

    __shared__ float sbm[64 * Kn];    // [c][k] (reads are warp-broadcast)
    __shared__ float sat[Kn * 128];   // [k][n] transposed attention

    const float* bb = g_b + ((b * Cn) + c0) * Kn;
#pragma unroll
    for (int t = 0; t < 4; t++) {
        int i = tid + t * 256;
        int row = i >> 4, k4 = i & 15;
        *(float4*)(sbm + row * Kn + k4 * 4) = *(const float4*)(bb + row * Kn + k4 * 4);
    }
    const float* ab = g_att + ((size_t)b * Nn + n0) * Kn;
    // 128 n-rows x 64 k = 8192 floats = 2048 float4 -> 8 passes of 256 threads
#pragma unroll
    for (int t = 0; t < 8; t++) {
        int i = tid + t * 256;                 // 0..2047
        int nn = i >> 4, k4 = i & 15;          // nn 0..127, k4 0..15
        float4 v = *(const float4*)(ab + (size_t)nn * Kn + k4 * 4);
        sat[(k4 * 4 + 0) * 128 + nn] = v.x;
        sat[(k4 * 4 + 1) * 128 + nn] = v.y;
        sat[(k4 * 4 + 2) * 128 + nn] = v.z;
        sat[(k4 * 4 + 3) * 128 + nn] = v.w;
    }
    __syncthreads();

    float acc[8][4];
#pragma unroll
    for (int r = 0; r < 8; r++)
#pragma unroll
        for (int j = 0; j < 4; j++) acc[r][j] = 0.f;

#pragma unroll
    for (int k = 0; k < Kn; k++) {
        float4 av = *(float4*)(sat + k * 128 + nx * 4);
        float aw[4] = {av.x, av.y, av.z, av.w};
#pragma unroll
        for (int r = 0; r < 8; r++) {
            float bvv = sbm[(cy * 8 + r) * Kn + k];
            acc[r][0] += bvv * aw[0];
            acc[r][1] += bvv * aw[1];
            acc[r][2] += bvv * aw[2];
            acc[r][3] += bvv * aw[3];
        }
    }

    float* ob = out + ((size_t)b * Cn + c0) * Nn + n0;
#pragma unroll
    for (int r = 0; r < 8; r++)
        *(float4*)(ob + (size_t)(cy * 8 + r) * Nn + nx * 4) =
            make_float4(acc[r][0], acc[r][1], acc[r][2], acc[r][3]);
}

// ---------------------------------------------------------------------------
extern "C" void kernel_launch(void* const* d_in, const int* in_sizes, int n_in,
                              void* d_out, int out_size) {
    const float* feats = (const float*)d_in[0];   // [16,512,64,64]
    const float* bases = (const float*)d_in[1];   // [1,512,64]
    float* out = (float*)d_out;
    (void)in_sizes; (void)n_in; (void)out_size;

    k_init<<<Kn, 128>>>(bases);

    for (int s = 0; s < NUM_STAGES; s++) {
        k_zero<<<(Bn * Cn * Kn + 255) / 256, 256>>>();
        {
            dim3 g(Nn / 128, Bn);
            k_att<<<g, 256>>>(feats);
        }
        {
            dim3 g(NCHUNK, Cn / 128, Bn);
            k_bnew<<<g, 256>>>(feats);
        }
        k_bnorm<<<Bn * Kn, 128>>>();
    }
    {
        dim3 g(Nn / 128, Cn / 64, Bn);
        k_recon<<<g, 256>>>(out);
    }
}